// round 3
// baseline (speedup 1.0000x reference)
#include <cuda_runtime.h>
#include <cstdint>
#include <math.h>

// Problem constants
#define B_  64
#define S_  512
#define E_  256
#define H_  512
#define O_  1000
#define NBLK 128   // persistent grid size

// packed fp32x2 FMA: d = a*b + d (elementwise on 2-wide fp32), exact fp32
#define FMA2(c, a, b) asm("fma.rn.f32x2 %0, %1, %2, %0;" : "+l"(c) : "l"(a), "l"(b))

__device__ __forceinline__ float2 u2f(unsigned long long u) {
    float2 f;
    asm("mov.b64 {%0, %1}, %2;" : "=f"(f.x), "=f"(f.y) : "l"(u));
    return f;
}

// ---------------- device scratch (no allocations allowed) ----------------
__device__ float g_h[2 * H_ * B_];              // [buf][j][b]
__device__ float g_xpre[67108864];              // [s][g][j][b] = 512*4*512*64
__device__ unsigned g_bar_count;
__device__ unsigned g_bar_gen;

// ---------------- grid barrier (all 128 CTAs co-resident) ----------------
__device__ __forceinline__ void grid_sync(unsigned target) {
    __syncthreads();
    if (threadIdx.x == 0) {
        __threadfence();
        unsigned old = atomicAdd(&g_bar_count, 1u);
        if (old == (unsigned)(NBLK - 1)) {
            atomicExch(&g_bar_count, 0u);
            __threadfence();
            atomicAdd(&g_bar_gen, 1u);
        } else {
            while (*(volatile unsigned*)&g_bar_gen < target) { __nanosleep(32); }
        }
        __threadfence();   // acquire side
    }
    __syncthreads();
}

__global__ void init_bar_kernel() {
    g_bar_count = 0u;
    g_bar_gen = 0u;
}

// ---------------- Kernel 1: input-part GEMM (parallel over all timesteps) ----------------
// xpre[s][g][j][b] = b_g[j] + sum_e embed_w[x[b,s], e] * W_g[512+e, j]
// grid: (8 jtiles, 4 gates, 512 steps), block: 256 threads, tile 64j x 64b, K=256
// f32x2 version: sE2 holds {e,e}-duplicated embeddings so the batch operand is a
// natural 64-bit pair; weight pairs {w_j, w_j+1} come packed for free from sW.
__global__ void __launch_bounds__(256) input_gemm_kernel(
    const int* __restrict__ x, const float* __restrict__ embed_w,
    const float* __restrict__ Wf, const float* __restrict__ Wi,
    const float* __restrict__ Wc, const float* __restrict__ Wo,
    const float* __restrict__ bf, const float* __restrict__ bi,
    const float* __restrict__ bc, const float* __restrict__ bo)
{
    const int jt = blockIdx.x;   // 0..7
    const int g  = blockIdx.y;   // 0..3
    const int s  = blockIdx.z;   // 0..511
    const float* Wg = (g == 0) ? Wf : (g == 1) ? Wi : (g == 2) ? Wc : Wo;
    const float* bg = (g == 0) ? bf : (g == 1) ? bi : (g == 2) ? bc : bo;

    __shared__ int    rows[B_];
    __shared__ float2 sE2[32 * 64];   // [e][b] duplicated {v,v}  (16 KB)
    __shared__ float  sW[32][64];     // [e][j]                    (8 KB)

    const int t = threadIdx.x;
    if (t < B_) rows[t] = x[t * S_ + s];
    __syncthreads();

    const int tb = t & 15;         // b group (4 b each)
    const int tj = t >> 4;         // j group (4 j each)

    // acc2[bq][jp] = {acc[bq][2jp], acc[bq][2jp+1]}
    unsigned long long acc2[4][2] = {{0ull,0ull},{0ull,0ull},{0ull,0ull},{0ull,0ull}};

    for (int e0 = 0; e0 < E_; e0 += 32) {
        // load emb chunk duplicated into sE2[e][b] = {v, v}
        {
            int b = t >> 2, sub = (t & 3) * 8;
            const float* src = embed_w + (size_t)rows[b] * E_ + e0 + sub;
            float4 v0 = *(const float4*)(src);
            float4 v1 = *(const float4*)(src + 4);
            sE2[(sub + 0) * 64 + b] = make_float2(v0.x, v0.x);
            sE2[(sub + 1) * 64 + b] = make_float2(v0.y, v0.y);
            sE2[(sub + 2) * 64 + b] = make_float2(v0.z, v0.z);
            sE2[(sub + 3) * 64 + b] = make_float2(v0.w, v0.w);
            sE2[(sub + 4) * 64 + b] = make_float2(v1.x, v1.x);
            sE2[(sub + 5) * 64 + b] = make_float2(v1.y, v1.y);
            sE2[(sub + 6) * 64 + b] = make_float2(v1.z, v1.z);
            sE2[(sub + 7) * 64 + b] = make_float2(v1.w, v1.w);
        }
        // load W chunk sW[e][j]
        {
            int e = t >> 3, jsub = (t & 7) * 8;
            const float* src = Wg + (size_t)(H_ + e0 + e) * H_ + jt * 64 + jsub;
            float4 v0 = *(const float4*)(src);
            float4 v1 = *(const float4*)(src + 4);
            *(float4*)&sW[e][jsub]     = v0;
            *(float4*)&sW[e][jsub + 4] = v1;
        }
        __syncthreads();
#pragma unroll
        for (int k = 0; k < 32; ++k) {
            ulonglong2 ha0 = *(ulonglong2*)&sE2[k * 64 + tb * 4];      // {b0,b0},{b1,b1}
            ulonglong2 ha1 = *(ulonglong2*)&sE2[k * 64 + tb * 4 + 2];  // {b2,b2},{b3,b3}
            ulonglong2 wp  = *(ulonglong2*)&sW[k][tj * 4];             // {w0,w1},{w2,w3}
            FMA2(acc2[0][0], ha0.x, wp.x); FMA2(acc2[0][1], ha0.x, wp.y);
            FMA2(acc2[1][0], ha0.y, wp.x); FMA2(acc2[1][1], ha0.y, wp.y);
            FMA2(acc2[2][0], ha1.x, wp.x); FMA2(acc2[2][1], ha1.x, wp.y);
            FMA2(acc2[3][0], ha1.y, wp.x); FMA2(acc2[3][1], ha1.y, wp.y);
        }
        __syncthreads();
    }

    // unpack accumulators
    float acc[4][4];
#pragma unroll
    for (int bq = 0; bq < 4; ++bq)
#pragma unroll
        for (int jp = 0; jp < 2; ++jp) {
            float2 f = u2f(acc2[bq][jp]);
            acc[bq][2 * jp]     = f.x;
            acc[bq][2 * jp + 1] = f.y;
        }

    float* outp = g_xpre + (size_t)(s * 4 + g) * H_ * B_;
#pragma unroll
    for (int ji = 0; ji < 4; ++ji) {
        int jg = jt * 64 + tj * 4 + ji;
        float bb = bg[jg];
        float4 v = make_float4(acc[0][ji] + bb, acc[1][ji] + bb,
                               acc[2][ji] + bb, acc[3][ji] + bb);
        *(float4*)&outp[(size_t)jg * B_ + tb * 4] = v;
    }
}

// ---------------- Kernel 2: persistent recurrent LSTM (f32x2) ----------------
// 128 CTAs x 128 threads; CTA owns 4 hidden units (16 gate cols).
// Dynamic SMEM 64KB: sWh [512][16] (32KB) + sH2 [64][64] float2 dup'd (32KB).
// warp w -> hidden unit j0+w; lane l -> batches 2l, 2l+1. c state in registers.
__global__ void __launch_bounds__(128, 1) lstm_persistent_kernel(
    const float* __restrict__ hidden_in, const float* __restrict__ c_in,
    const float* __restrict__ Wf, const float* __restrict__ Wi,
    const float* __restrict__ Wc, const float* __restrict__ Wo,
    float* __restrict__ d_out)
{
    extern __shared__ float dsm[];
    float*  sWh = dsm;                         // [k][jj*4+g] flat, 512*16 floats
    float2* sH2 = (float2*)(dsm + 512 * 16);   // [k_local][b] duplicated {h,h}

    const int tid  = threadIdx.x;
    const int w    = tid >> 5;
    const int lane = tid & 31;
    const int j0   = blockIdx.x * 4;
    const int jme  = j0 + w;
    const int b0   = lane * 2;

    const float* W4[4] = {Wf, Wi, Wc, Wo};
    // Load weight tile once for whole run
    for (int k = tid; k < H_; k += 128) {
#pragma unroll
        for (int jj = 0; jj < 4; ++jj)
#pragma unroll
            for (int g = 0; g < 4; ++g)
                sWh[k * 16 + jj * 4 + g] = W4[g][(size_t)k * H_ + j0 + jj];
    }

    // Initial state
    float c0 = c_in[(b0 + 0) * H_ + jme];
    float c1 = c_in[(b0 + 1) * H_ + jme];
    g_h[jme * B_ + b0 + 0] = hidden_in[(b0 + 0) * H_ + jme];
    g_h[jme * B_ + b0 + 1] = hidden_in[(b0 + 1) * H_ + jme];
    grid_sync(1u);

    for (int s = 0; s < S_; ++s) {
        const int rbuf = s & 1;
        const int wbuf = rbuf ^ 1;
        const float* hsrc = g_h + rbuf * (H_ * B_);

        // prefetch h chunk 0 into registers (L2-only loads: no stale L1)
        float4 pre[8];
        {
            const float4* src = (const float4*)hsrc;
#pragma unroll
            for (int i = 0; i < 8; ++i) pre[i] = __ldcg(src + tid + i * 128);
        }
        // prefetch precomputed input part (consumed only in epilogue)
        float xp[8];
        {
            const float* xb = g_xpre + (size_t)(s * 4) * H_ * B_;
#pragma unroll
            for (int g = 0; g < 4; ++g) {
                float2 v = *(const float2*)&xb[(size_t)(g * H_ + jme) * B_ + b0];
                xp[g] = v.x; xp[4 + g] = v.y;
            }
        }

        // acc pairs: [0]={f,i}@b0 [1]={c,o}@b0 [2]={f,i}@b1 [3]={c,o}@b1
        unsigned long long a0 = 0ull, a1 = 0ull, a2 = 0ull, a3 = 0ull;

        for (int kc = 0; kc < 8; ++kc) {
            __syncthreads();
            // stage chunk duplicated: sH2[k][b] = {h, h}
            {
#pragma unroll
                for (int i = 0; i < 8; ++i) {
                    float4 v = pre[i];
                    int f = tid + i * 128;          // float4 index in chunk
                    int k = f >> 4, b = (f & 15) * 4;
                    float4* d = (float4*)&sH2[k * 64 + b];
                    d[0] = make_float4(v.x, v.x, v.y, v.y);
                    d[1] = make_float4(v.z, v.z, v.w, v.w);
                }
            }
            __syncthreads();
            if (kc < 7) {
                const float4* src = (const float4*)(hsrc + (kc + 1) * 64 * 64);
#pragma unroll
                for (int i = 0; i < 8; ++i) pre[i] = __ldcg(src + tid + i * 128);
            }
#pragma unroll
            for (int k = 0; k < 64; ++k) {
                ulonglong2 hd = *(ulonglong2*)&sH2[k * 64 + b0];          // {hb0,hb0},{hb1,hb1}
                ulonglong2 wp = *(ulonglong2*)&sWh[(kc * 64 + k) * 16 + w * 4]; // {wf,wi},{wc,wo}
                FMA2(a0, hd.x, wp.x);
                FMA2(a1, hd.x, wp.y);
                FMA2(a2, hd.y, wp.x);
                FMA2(a3, hd.y, wp.y);
            }
        }

        float2 fi0 = u2f(a0), co0 = u2f(a1), fi1 = u2f(a2), co1 = u2f(a3);

        // gates + state update (b0 and b0+1)
        float f0  = 1.f / (1.f + expf(-(fi0.x + xp[0])));
        float i0  = 1.f / (1.f + expf(-(fi0.y + xp[1])));
        float ct0 = tanhf(co0.x + xp[2]);
        float o0  = 1.f / (1.f + expf(-(co0.y + xp[3])));
        c0 = f0 * c0 + i0 * ct0;
        float h0 = o0 * tanhf(c0);

        float f1  = 1.f / (1.f + expf(-(fi1.x + xp[4])));
        float i1  = 1.f / (1.f + expf(-(fi1.y + xp[5])));
        float ct1 = tanhf(co1.x + xp[6]);
        float o1  = 1.f / (1.f + expf(-(co1.y + xp[7])));
        c1 = f1 * c1 + i1 * ct1;
        float h1 = o1 * tanhf(c1);

        *(float2*)&g_h[wbuf * (H_ * B_) + jme * B_ + b0] = make_float2(h0, h1);
        if (s == S_ - 1) {
            d_out[B_ * O_ + (b0 + 0) * H_ + jme] = h0;
            d_out[B_ * O_ + (b0 + 1) * H_ + jme] = h1;
        }
        grid_sync((unsigned)(s + 2));
    }
}

// ---------------- Kernel 3: dense head  out[b,o] = h[b]·W_d[:,o] + b_d[o] ----------------
// grid (4 o-tiles, 32 b-tiles of 2), 256 threads -> 128 CTAs for latency hiding.
__global__ void __launch_bounds__(256) dense_out_kernel(
    const float* __restrict__ Wd, const float* __restrict__ bd,
    float* __restrict__ d_out)
{
    const int o  = blockIdx.x * 256 + threadIdx.x;
    const int b0 = blockIdx.y * 2;
    __shared__ float sh[2][H_];
    const float* hsrc = d_out + B_ * O_;   // hidden written by persistent kernel

    for (int idx = threadIdx.x; idx < 2 * H_; idx += 256) {
        int bi = idx >> 9;
        int j  = idx & (H_ - 1);
        sh[bi][j] = hsrc[(b0 + bi) * H_ + j];
    }
    __syncthreads();

    if (o < O_) {
        float bias = bd[o];
        float acc0 = bias, acc1 = bias;
#pragma unroll 8
        for (int j = 0; j < H_; ++j) {
            float wv = Wd[(size_t)j * O_ + o];
            acc0 += sh[0][j] * wv;
            acc1 += sh[1][j] * wv;
        }
        d_out[(b0 + 0) * O_ + o] = acc0;
        d_out[(b0 + 1) * O_ + o] = acc1;
    }
}

// ---------------- launch ----------------
extern "C" void kernel_launch(void* const* d_in, const int* in_sizes, int n_in,
                              void* d_out, int out_size) {
    const int*   x        = (const int*)  d_in[0];
    const float* hidden   = (const float*)d_in[1];
    const float* c        = (const float*)d_in[2];
    const float* embed_w  = (const float*)d_in[3];
    const float* W_f      = (const float*)d_in[4];
    const float* b_f      = (const float*)d_in[5];
    const float* W_i      = (const float*)d_in[6];
    const float* b_i      = (const float*)d_in[7];
    const float* W_c      = (const float*)d_in[8];
    const float* b_c      = (const float*)d_in[9];
    const float* W_o      = (const float*)d_in[10];
    const float* b_o      = (const float*)d_in[11];
    const float* W_d      = (const float*)d_in[12];
    const float* b_d      = (const float*)d_in[13];
    float* out = (float*)d_out;

    static bool attr_set = false;
    if (!attr_set) {
        cudaFuncSetAttribute(lstm_persistent_kernel,
                             cudaFuncAttributeMaxDynamicSharedMemorySize, 64 * 1024);
        attr_set = true;
    }

    init_bar_kernel<<<1, 1>>>();

    dim3 g1(8, 4, S_);
    input_gemm_kernel<<<g1, 256>>>(x, embed_w, W_f, W_i, W_c, W_o,
                                   b_f, b_i, b_c, b_o);

    lstm_persistent_kernel<<<NBLK, 128, 64 * 1024>>>(hidden, c, W_f, W_i, W_c, W_o, out);

    dim3 g3(4, 32);
    dense_out_kernel<<<g3, 256>>>(W_d, b_d, out);
}

// round 5
// speedup vs baseline: 1.6253x; 1.6253x over previous
#include <cuda_runtime.h>
#include <cstdint>
#include <math.h>

// Problem constants
#define B_  64
#define S_  512
#define E_  256
#define H_  512
#define O_  1000
#define NBLK 128   // persistent grid size

// ---------------- device scratch (no allocations allowed) ----------------
__device__ float g_h[2 * H_ * B_];              // [buf][j][b]
__device__ float g_xpre[67108864];              // [s][g][j][b] = 512*4*512*64
__device__ int   g_flag[NBLK * 32];             // per-CTA progress flag, 128B apart

__device__ __forceinline__ int ld_acquire_gpu(const int* p) {
    int v;
    asm volatile("ld.acquire.gpu.global.s32 %0, [%1];" : "=r"(v) : "l"(p) : "memory");
    return v;
}
__device__ __forceinline__ void st_release_gpu(int* p, int v) {
    asm volatile("st.release.gpu.global.s32 [%0], %1;" :: "l"(p), "r"(v) : "memory");
}

__global__ void init_flags_kernel() {
    g_flag[threadIdx.x * 32] = 0;
}

// ---------------- Kernel 1: input-part GEMM (parallel over all timesteps) ----------------
// xpre[s][g][j][b] = b_g[j] + sum_e embed_w[x[b,s], e] * W_g[512+e, j]
// grid: (8 jtiles, 4 gates, 512 steps), block: 256 threads, tile 64j x 64b, K=256
__global__ void __launch_bounds__(256) input_gemm_kernel(
    const int* __restrict__ x, const float* __restrict__ embed_w,
    const float* __restrict__ Wf, const float* __restrict__ Wi,
    const float* __restrict__ Wc, const float* __restrict__ Wo,
    const float* __restrict__ bf, const float* __restrict__ bi,
    const float* __restrict__ bc, const float* __restrict__ bo)
{
    const int jt = blockIdx.x;   // 0..7
    const int g  = blockIdx.y;   // 0..3
    const int s  = blockIdx.z;   // 0..511
    const float* Wg = (g == 0) ? Wf : (g == 1) ? Wi : (g == 2) ? Wc : Wo;
    const float* bg = (g == 0) ? bf : (g == 1) ? bi : (g == 2) ? bc : bo;

    __shared__ int   rows[B_];
    __shared__ float sE[32][64];   // [e][b]
    __shared__ float sW[32][64];   // [e][j]

    const int t = threadIdx.x;
    if (t < B_) rows[t] = x[t * S_ + s];
    __syncthreads();

    const int tb = t & 15;         // b group (4 b each)
    const int tj = t >> 4;         // j group (4 j each)
    float acc[4][4];
#pragma unroll
    for (int a = 0; a < 4; ++a)
#pragma unroll
        for (int bqq = 0; bqq < 4; ++bqq) acc[a][bqq] = 0.f;

    for (int e0 = 0; e0 < E_; e0 += 32) {
        // load emb chunk, transposed into sE[e][b]
        {
            int b = t >> 2, sub = (t & 3) * 8;
            const float* src = embed_w + (size_t)rows[b] * E_ + e0 + sub;
            float4 v0 = *(const float4*)(src);
            float4 v1 = *(const float4*)(src + 4);
            sE[sub + 0][b] = v0.x; sE[sub + 1][b] = v0.y;
            sE[sub + 2][b] = v0.z; sE[sub + 3][b] = v0.w;
            sE[sub + 4][b] = v1.x; sE[sub + 5][b] = v1.y;
            sE[sub + 6][b] = v1.z; sE[sub + 7][b] = v1.w;
        }
        // load W chunk sW[e][j]
        {
            int e = t >> 3, jsub = (t & 7) * 8;
            const float* src = Wg + (size_t)(H_ + e0 + e) * H_ + jt * 64 + jsub;
            float4 v0 = *(const float4*)(src);
            float4 v1 = *(const float4*)(src + 4);
            *(float4*)&sW[e][jsub]     = v0;
            *(float4*)&sW[e][jsub + 4] = v1;
        }
        __syncthreads();
#pragma unroll
        for (int k = 0; k < 32; ++k) {
            float4 rb = *(float4*)&sE[k][tb * 4];
            float4 rw = *(float4*)&sW[k][tj * 4];
            acc[0][0] += rb.x * rw.x; acc[0][1] += rb.x * rw.y; acc[0][2] += rb.x * rw.z; acc[0][3] += rb.x * rw.w;
            acc[1][0] += rb.y * rw.x; acc[1][1] += rb.y * rw.y; acc[1][2] += rb.y * rw.z; acc[1][3] += rb.y * rw.w;
            acc[2][0] += rb.z * rw.x; acc[2][1] += rb.z * rw.y; acc[2][2] += rb.z * rw.z; acc[2][3] += rb.z * rw.w;
            acc[3][0] += rb.w * rw.x; acc[3][1] += rb.w * rw.y; acc[3][2] += rb.w * rw.z; acc[3][3] += rb.w * rw.w;
        }
        __syncthreads();
    }

    float* outp = g_xpre + (size_t)(s * 4 + g) * H_ * B_;
#pragma unroll
    for (int ji = 0; ji < 4; ++ji) {
        int jg = jt * 64 + tj * 4 + ji;
        float bb = bg[jg];
        float4 v = make_float4(acc[0][ji] + bb, acc[1][ji] + bb,
                               acc[2][ji] + bb, acc[3][ji] + bb);
        *(float4*)&outp[(size_t)jg * B_ + tb * 4] = v;
    }
}

// ---------------- Kernel 2: persistent recurrent LSTM, flag-based full barrier ----
// 128 CTAs x 128 threads; CTA owns 4 hidden units (16 gate cols), weights in SMEM.
// warp w -> hidden unit j0+w; lane l -> batches 2l, 2l+1. c state in registers.
// Per-step sync (cooperative-groups grid-sync idiom, distributed flags):
//   publish: write h slice -> __threadfence -> bar -> tid0 st.release.gpu flag=s+2
//   wait:    thread t polls flag[t] with ld.acquire.gpu until >= s+1 -> bar
// No same-address atomic serialization (R2's 128x32cyc chain), formally
// acquire/release-correct (R4's relaxed-poll hole closed).
// WAR safety: before writing h_{s+1} (buffer (s+1)&1), the step-s barrier has
// observed all flags >= s+1, i.e. every CTA finished step s-1 and thus all
// reads of h_{s-1} from that same buffer.
__global__ void __launch_bounds__(128, 1) lstm_persistent_kernel(
    const float* __restrict__ hidden_in, const float* __restrict__ c_in,
    const float* __restrict__ Wf, const float* __restrict__ Wi,
    const float* __restrict__ Wc, const float* __restrict__ Wo,
    float* __restrict__ d_out)
{
    __shared__ float sWh[512][16];   // [k][jj*4 + g], g order {f,i,c,o}  (32 KB)
    __shared__ float sH[64][64];     // [k_local][b]                       (16 KB)

    const int tid  = threadIdx.x;
    const int w    = tid >> 5;
    const int lane = tid & 31;
    const int j0   = blockIdx.x * 4;
    const int jme  = j0 + w;
    const int b0   = lane * 2;

    const float* W4[4] = {Wf, Wi, Wc, Wo};
    // Load weight tile once for whole run
    for (int k = tid; k < H_; k += 128) {
#pragma unroll
        for (int jj = 0; jj < 4; ++jj)
#pragma unroll
            for (int g = 0; g < 4; ++g)
                sWh[k][jj * 4 + g] = W4[g][(size_t)k * H_ + j0 + jj];
    }

    // Initial state: publish h_0 and flag = 1
    float c0 = c_in[(b0 + 0) * H_ + jme];
    float c1 = c_in[(b0 + 1) * H_ + jme];
    g_h[jme * B_ + b0 + 0] = hidden_in[(b0 + 0) * H_ + jme];
    g_h[jme * B_ + b0 + 1] = hidden_in[(b0 + 1) * H_ + jme];
    __threadfence();
    __syncthreads();
    if (tid == 0) st_release_gpu(&g_flag[blockIdx.x * 32], 1);

    for (int s = 0; s < S_; ++s) {
        const int rbuf = s & 1;
        const int wbuf = rbuf ^ 1;
        const int target = s + 1;               // flag value meaning "h_s ready"
        const float* hsrc = g_h + rbuf * (H_ * B_);

        // prefetch precomputed input part (static data; safe before barrier)
        float xp[8];
        {
            const float* xb = g_xpre + (size_t)(s * 4) * H_ * B_;
#pragma unroll
            for (int g = 0; g < 4; ++g) {
                float2 v = *(const float2*)&xb[(size_t)(g * H_ + jme) * B_ + b0];
                xp[g] = v.x; xp[4 + g] = v.y;
            }
        }

        // full step barrier: thread t acquires flag of CTA t
        {
            const int* fl = &g_flag[tid * 32];
            while (ld_acquire_gpu(fl) < target) { }
        }
        __syncthreads();

        // prefetch chunk 0 (L2-only loads: no stale L1)
        float4 pre[8];
        {
            const float4* src = (const float4*)hsrc;
#pragma unroll
            for (int i = 0; i < 8; ++i) pre[i] = __ldcg(src + tid + i * 128);
        }

        float acc[8] = {0.f, 0.f, 0.f, 0.f, 0.f, 0.f, 0.f, 0.f};
        for (int kc = 0; kc < 8; ++kc) {
            __syncthreads();                    // sH safe to overwrite
            {
                float4* dst = (float4*)sH;
#pragma unroll
                for (int i = 0; i < 8; ++i) dst[tid + i * 128] = pre[i];
            }
            __syncthreads();
            if (kc < 7) {
                const float4* src = (const float4*)(hsrc + (kc + 1) * 64 * 64);
#pragma unroll
                for (int i = 0; i < 8; ++i) pre[i] = __ldcg(src + tid + i * 128);
            }
#pragma unroll
            for (int k = 0; k < 64; ++k) {
                float2 hv = *(float2*)&sH[k][b0];
                float4 wv = *(float4*)&sWh[kc * 64 + k][w * 4];
                acc[0] += hv.x * wv.x; acc[1] += hv.x * wv.y;
                acc[2] += hv.x * wv.z; acc[3] += hv.x * wv.w;
                acc[4] += hv.y * wv.x; acc[5] += hv.y * wv.y;
                acc[6] += hv.y * wv.z; acc[7] += hv.y * wv.w;
            }
        }

        // gates + state update (b0 and b0+1)
        float f0  = 1.f / (1.f + expf(-(acc[0] + xp[0])));
        float i0  = 1.f / (1.f + expf(-(acc[1] + xp[1])));
        float ct0 = tanhf(acc[2] + xp[2]);
        float o0  = 1.f / (1.f + expf(-(acc[3] + xp[3])));
        c0 = f0 * c0 + i0 * ct0;
        float h0 = o0 * tanhf(c0);

        float f1  = 1.f / (1.f + expf(-(acc[4] + xp[4])));
        float i1  = 1.f / (1.f + expf(-(acc[5] + xp[5])));
        float ct1 = tanhf(acc[6] + xp[6]);
        float o1  = 1.f / (1.f + expf(-(acc[7] + xp[7])));
        c1 = f1 * c1 + i1 * ct1;
        float h1 = o1 * tanhf(c1);

        if (s < S_ - 1) {
            *(float2*)&g_h[wbuf * (H_ * B_) + jme * B_ + b0] = make_float2(h0, h1);
            __threadfence();
            __syncthreads();
            if (tid == 0) st_release_gpu(&g_flag[blockIdx.x * 32], s + 2);
        } else {
            d_out[B_ * O_ + (b0 + 0) * H_ + jme] = h0;
            d_out[B_ * O_ + (b0 + 1) * H_ + jme] = h1;
        }
    }
}

// ---------------- Kernel 3: dense head  out[b,o] = h[b]·W_d[:,o] + b_d[o] ----------------
// grid (4 o-tiles, 32 b-tiles of 2), 256 threads -> 128 CTAs for latency hiding.
__global__ void __launch_bounds__(256) dense_out_kernel(
    const float* __restrict__ Wd, const float* __restrict__ bd,
    float* __restrict__ d_out)
{
    const int o  = blockIdx.x * 256 + threadIdx.x;
    const int b0 = blockIdx.y * 2;
    __shared__ float sh[2][H_];
    const float* hsrc = d_out + B_ * O_;   // hidden written by persistent kernel

    for (int idx = threadIdx.x; idx < 2 * H_; idx += 256) {
        int bi = idx >> 9;
        int j  = idx & (H_ - 1);
        sh[bi][j] = hsrc[(b0 + bi) * H_ + j];
    }
    __syncthreads();

    if (o < O_) {
        float bias = bd[o];
        float acc0 = bias, acc1 = bias;
#pragma unroll 8
        for (int j = 0; j < H_; ++j) {
            float wv = Wd[(size_t)j * O_ + o];
            acc0 += sh[0][j] * wv;
            acc1 += sh[1][j] * wv;
        }
        d_out[(b0 + 0) * O_ + o] = acc0;
        d_out[(b0 + 1) * O_ + o] = acc1;
    }
}

// ---------------- launch ----------------
extern "C" void kernel_launch(void* const* d_in, const int* in_sizes, int n_in,
                              void* d_out, int out_size) {
    const int*   x        = (const int*)  d_in[0];
    const float* hidden   = (const float*)d_in[1];
    const float* c        = (const float*)d_in[2];
    const float* embed_w  = (const float*)d_in[3];
    const float* W_f      = (const float*)d_in[4];
    const float* b_f      = (const float*)d_in[5];
    const float* W_i      = (const float*)d_in[6];
    const float* b_i      = (const float*)d_in[7];
    const float* W_c      = (const float*)d_in[8];
    const float* b_c      = (const float*)d_in[9];
    const float* W_o      = (const float*)d_in[10];
    const float* b_o      = (const float*)d_in[11];
    const float* W_d      = (const float*)d_in[12];
    const float* b_d      = (const float*)d_in[13];
    float* out = (float*)d_out;

    init_flags_kernel<<<1, NBLK>>>();

    dim3 g1(8, 4, S_);
    input_gemm_kernel<<<g1, 256>>>(x, embed_w, W_f, W_i, W_c, W_o,
                                   b_f, b_i, b_c, b_o);

    lstm_persistent_kernel<<<NBLK, 128>>>(hidden, c, W_f, W_i, W_c, W_o, out);

    dim3 g3(4, 32);
    dense_out_kernel<<<g3, 256>>>(W_d, b_d, out);
}